// round 8
// baseline (speedup 1.0000x reference)
#include <cuda_runtime.h>
#include <cstdint>

#define BATCH 32
#define CIN   3
#define HH    64
#define WW    64
#define HC    128
#define NCTA  128
#define NTHR  512
#define CLU   4
#define AST   132                  // padded A row stride (floats): 528B = 4-bank skew

// smem layout (floats)
#define A0_OFF 0                   // (WW+1) x AST = 65*132 = 8580, row 0 = zero pad (w=-1)
#define A1_OFF 8580
#define W_OFF  17160               // 256 x 128: [(tap*128+ci)*128 + j_*8 + g*2 + p]
#define WI_OFF 49928               // 6 x 128:   [(tap*3+cn)*128 + j_*8 + g*2 + p]
#define SMEM_FLOATS 50696          // 202784 bytes

__device__ __forceinline__ unsigned long long pack2(float lo, float hi) {
    unsigned long long r;
    asm("mov.b64 %0, {%1, %2};" : "=l"(r) : "f"(lo), "f"(hi));
    return r;
}
__device__ __forceinline__ void unpack2(unsigned long long v, float& lo, float& hi) {
    asm("mov.b64 {%0, %1}, %2;" : "=f"(lo), "=f"(hi) : "l"(v));
}
__device__ __forceinline__ unsigned long long fma2(unsigned long long a,
                                                   unsigned long long b,
                                                   unsigned long long c) {
    unsigned long long d;
    asm("fma.rn.f32x2 %0, %1, %2, %3;" : "=l"(d) : "l"(a), "l"(b), "l"(c));
    return d;
}
__device__ __forceinline__ float sigm(float v) { return 1.f / (1.f + __expf(-v)); }

__global__ __launch_bounds__(NTHR, 1) __cluster_dims__(CLU, 1, 1)
void rowlstm_kernel(const float* __restrict__ x,
                    const float* __restrict__ W_is,
                    const float* __restrict__ b_is,
                    const float* __restrict__ W_ss,
                    const float* __restrict__ b_ss,
                    const float* __restrict__ h0,
                    const float* __restrict__ c0,
                    float* __restrict__ out)
{
    extern __shared__ float sm[];
    float* W_s  = sm + W_OFF;
    float* WI_s = sm + WI_OFF;

    const int tid = threadIdx.x;
    const int b   = blockIdx.x >> 2;
    unsigned int rank;
    asm("mov.u32 %0, %%cluster_ctarank;" : "=r"(rank));
    const int t = (int)rank;                 // ci-tile 0..3

    // ---- one-time loads ----
    // W_s[(tap*128+ci)*128 + j_*8 + g*2 + p], col = g*32 + j_*2 + p (thread-contiguous 8)
    for (int idx = tid; idx < 32768; idx += NTHR) {
        int k = idx >> 7, r = idx & 127;
        int tap = k >> 7, ci = k & 127;
        int jj = r >> 3, q = r & 7;
        int g = q >> 1, p = q & 1;
        int co = g * HC + t * 32 + jj * 2 + p;
        W_s[idx] = W_ss[(co * HC + ci) * 3 + tap];
    }
    // WI_s[(tap*3+cn)*128 + j_*8 + g*2 + p]
    for (int idx = tid; idx < 768; idx += NTHR) {
        int k = idx >> 7, r = idx & 127;
        int tap = k / 3, cn = k - tap * 3;
        int jj = r >> 3, q = r & 7;
        int g = q >> 1, p = q & 1;
        int co = g * HC + t * 32 + jj * 2 + p;
        WI_s[idx] = W_is[(co * CIN + cn) * 3 + tap];
    }
    // A0 <- full h0 (all 128 ci), pad row 0 of both buffers zero
    for (int idx = tid; idx < 8192; idx += NTHR) {
        int w = idx >> 7, ci = idx & 127;
        sm[A0_OFF + (w + 1) * AST + ci] = h0[ci * WW + w];
    }
    for (int idx = tid; idx < AST; idx += NTHR) {
        sm[A0_OFF + idx] = 0.f;
        sm[A1_OFF + idx] = 0.f;
    }

    // warp-shaped mapping: 16 warps; each warp spans 4 distinct j_, 8 distinct i5
    const int wid  = tid >> 5;
    const int lane = tid & 31;
    const int j_ = (wid & 3) * 4 + (lane >> 3);     // 0..15
    const int i5 = (wid >> 2) * 8 + (lane & 7);     // 0..31 ; w = wi*32 + i5, wi in {0,1}
    const int j2 = j_ << 1;
    const int j8 = j_ << 3;

    // per-thread persistent state: bias pairs + cell state registers
    unsigned long long bias2[4];
    #pragma unroll
    for (int g = 0; g < 4; g++) {
        int co = g * HC + t * 32 + j2;
        bias2[g] = pack2(b_is[co] + b_ss[co], b_is[co + 1] + b_ss[co + 1]);
    }
    float creg[2][2];
    #pragma unroll
    for (int wi = 0; wi < 2; wi++) {
        int w = wi * 32 + i5;
        creg[wi][0] = c0[(t * 32 + j2) * WW + w];
        creg[wi][1] = c0[(t * 32 + j2 + 1) * WW + w];
    }

    // peer smem base addresses (shared::cluster window) for DSMEM h exchange
    unsigned int mybase;
    asm("{ .reg .u64 a; cvta.to.shared.u64 a, %1; cvt.u32.u64 %0, a; }"
        : "=r"(mybase) : "l"(sm));
    unsigned int peer[CLU];
    #pragma unroll
    for (int r = 0; r < CLU; r++)
        asm("mapa.shared::cluster.u32 %0, %1, %2;" : "=r"(peer[r]) : "r"(mybase), "r"(r));

    __syncthreads();   // local init (W_s, WI_s, A0) visible block-wide

    for (int s = 0; s < HH; s++) {
        const float* Ac = sm + ((s & 1) ? A1_OFF : A0_OFF);
        const unsigned int nextOffB = (unsigned int)(((s & 1) ? A0_OFF : A1_OFF) * 4);

        // ---- acc starts at bias, add x-projection (LDGs overlap following GEMM) ----
        unsigned long long acc[2][4];
        #pragma unroll
        for (int wi = 0; wi < 2; wi++)
            #pragma unroll
            for (int g = 0; g < 4; g++) acc[wi][g] = bias2[g];

        {
            float xr[2][3][2];
            #pragma unroll
            for (int wi = 0; wi < 2; wi++) {
                int w = wi * 32 + i5;
                #pragma unroll
                for (int cn = 0; cn < CIN; cn++) {
                    const float* xb = x + ((b * CIN + cn) * HH + s) * WW;
                    xr[wi][cn][0] = (w > 0) ? xb[w - 1] : 0.f;
                    xr[wi][cn][1] = xb[w];
                }
            }
            #pragma unroll
            for (int tap = 0; tap < 2; tap++)
                #pragma unroll
                for (int cn = 0; cn < CIN; cn++) {
                    const float* wr = WI_s + (tap * 3 + cn) * 128 + j8;
                    ulonglong2 wa  = *(const ulonglong2*)wr;        // gates 0,1
                    ulonglong2 wb2 = *(const ulonglong2*)(wr + 4);  // gates 2,3
                    #pragma unroll
                    for (int wi = 0; wi < 2; wi++) {
                        unsigned long long xp = pack2(xr[wi][cn][tap], xr[wi][cn][tap]);
                        acc[wi][0] = fma2(xp, wa.x,  acc[wi][0]);
                        acc[wi][1] = fma2(xp, wa.y,  acc[wi][1]);
                        acc[wi][2] = fma2(xp, wb2.x, acc[wi][2]);
                        acc[wi][3] = fma2(xp, wb2.y, acc[wi][3]);
                    }
                }
        }

        // ---- GEMM: (2 w) x (4 gates x 2 ci) over K = 2 taps x 128 ci ----
        for (int cb = 0; cb < HC; cb += 4) {
            float4 aL4[2], aC4[2];
            #pragma unroll
            for (int wi = 0; wi < 2; wi++) {
                int wp = wi * 32 + i5;
                aL4[wi] = *(const float4*)(Ac + wp * AST + cb);
                aC4[wi] = *(const float4*)(Ac + (wp + 1) * AST + cb);
            }
            #pragma unroll
            for (int u = 0; u < 4; u++) {
                const float* wr0 = W_s + (cb + u) * 128 + j8;
                const float* wr1 = wr0 + 128 * 128;
                ulonglong2 w0a = *(const ulonglong2*)wr0;        // tap0 gates 0,1
                ulonglong2 w0b = *(const ulonglong2*)(wr0 + 4);  // tap0 gates 2,3
                ulonglong2 w1a = *(const ulonglong2*)wr1;        // tap1 gates 0,1
                ulonglong2 w1b = *(const ulonglong2*)(wr1 + 4);  // tap1 gates 2,3
                #pragma unroll
                for (int wi = 0; wi < 2; wi++) {
                    float aL = ((const float*)&aL4[wi])[u];
                    float aC = ((const float*)&aC4[wi])[u];
                    unsigned long long aLp = pack2(aL, aL);
                    unsigned long long aCp = pack2(aC, aC);
                    acc[wi][0] = fma2(aLp, w0a.x, acc[wi][0]);
                    acc[wi][1] = fma2(aLp, w0a.y, acc[wi][1]);
                    acc[wi][2] = fma2(aLp, w0b.x, acc[wi][2]);
                    acc[wi][3] = fma2(aLp, w0b.y, acc[wi][3]);
                    acc[wi][0] = fma2(aCp, w1a.x, acc[wi][0]);
                    acc[wi][1] = fma2(aCp, w1a.y, acc[wi][1]);
                    acc[wi][2] = fma2(aCp, w1b.x, acc[wi][2]);
                    acc[wi][3] = fma2(aCp, w1b.y, acc[wi][3]);
                }
            }
        }

        // ---- gates -> c,h in registers; write out + h to all 4 cluster CTAs ----
        #pragma unroll
        for (int wi = 0; wi < 2; wi++) {
            int w = wi * 32 + i5;
            float gv[4][2];
            #pragma unroll
            for (int g = 0; g < 4; g++) {
                float a0, a1;
                unpack2(acc[wi][g], a0, a1);
                gv[g][0] = sigm(a0);
                gv[g][1] = sigm(a1);
            }
            float hp[2];
            #pragma unroll
            for (int p = 0; p < 2; p++) {
                float cn2 = gv[1][p] * creg[wi][p] + gv[2][p] * gv[3][p];
                creg[wi][p] = cn2;
                float h = gv[0][p] * tanhf(cn2);
                hp[p] = h;
                out[((b * HC + t * 32 + j2 + p) * HH + s) * WW + w] = h;
            }
            unsigned long long hpair = pack2(hp[0], hp[1]);
            unsigned int off = nextOffB + (unsigned int)(((w + 1) * AST + t * 32 + j2) * 4);
            #pragma unroll
            for (int r = 0; r < CLU; r++)
                asm volatile("st.shared::cluster.b64 [%0], %1;"
                             :: "r"(peer[r] + off), "l"(hpair) : "memory");
        }

        // one cluster barrier per step: h(s) visible in everyone's A_next
        asm volatile("barrier.cluster.arrive.aligned;" ::: "memory");
        asm volatile("barrier.cluster.wait.aligned;" ::: "memory");
    }
}

extern "C" void kernel_launch(void* const* d_in, const int* in_sizes, int n_in,
                              void* d_out, int out_size) {
    const float* x    = (const float*)d_in[0];
    const float* W_is = (const float*)d_in[1];
    const float* b_is = (const float*)d_in[2];
    const float* W_ss = (const float*)d_in[3];
    const float* b_ss = (const float*)d_in[4];
    const float* h0   = (const float*)d_in[5];
    const float* c0   = (const float*)d_in[6];
    float* out = (float*)d_out;

    size_t smem = (size_t)SMEM_FLOATS * sizeof(float);
    cudaFuncSetAttribute(rowlstm_kernel,
                         cudaFuncAttributeMaxDynamicSharedMemorySize, (int)smem);
    rowlstm_kernel<<<NCTA, NTHR, smem>>>(x, W_is, b_is, W_ss, b_ss, h0, c0, out);
}

// round 9
// speedup vs baseline: 1.0003x; 1.0003x over previous
#include <cuda_runtime.h>
#include <cstdint>

#define BATCH 32
#define CIN   3
#define HH    64
#define WW    64
#define HC    128
#define NCTA  128
#define NTHR  512
#define CLU   4
#define AST   132                  // padded A row stride (floats): 528B = 4-bank skew

// smem layout (floats)
#define A0_OFF 0                   // (WW+1) x AST = 65*132 = 8580, row 0 = zero pad (w=-1)
#define A1_OFF 8580
#define W_OFF  17160               // 256 x 128: [(tap*128+ci)*128 + j_*8 + g*2 + p]
#define WI_OFF 49928               // 6 x 128:   [(tap*3+cn)*128 + j_*8 + g*2 + p]
#define SMEM_FLOATS 50696          // 202784 bytes

__device__ __forceinline__ unsigned long long pack2(float lo, float hi) {
    unsigned long long r;
    asm("mov.b64 %0, {%1, %2};" : "=l"(r) : "f"(lo), "f"(hi));
    return r;
}
__device__ __forceinline__ void unpack2(unsigned long long v, float& lo, float& hi) {
    asm("mov.b64 {%0, %1}, %2;" : "=f"(lo), "=f"(hi) : "l"(v));
}
__device__ __forceinline__ unsigned long long fma2(unsigned long long a,
                                                   unsigned long long b,
                                                   unsigned long long c) {
    unsigned long long d;
    asm("fma.rn.f32x2 %0, %1, %2, %3;" : "=l"(d) : "l"(a), "l"(b), "l"(c));
    return d;
}
__device__ __forceinline__ float sigm(float v) { return 1.f / (1.f + __expf(-v)); }

__global__ __launch_bounds__(NTHR, 1) __cluster_dims__(CLU, 1, 1)
void rowlstm_kernel(const float* __restrict__ x,
                    const float* __restrict__ W_is,
                    const float* __restrict__ b_is,
                    const float* __restrict__ W_ss,
                    const float* __restrict__ b_ss,
                    const float* __restrict__ h0,
                    const float* __restrict__ c0,
                    float* __restrict__ out)
{
    extern __shared__ float sm[];
    float* W_s  = sm + W_OFF;
    float* WI_s = sm + WI_OFF;

    const int tid = threadIdx.x;
    const int b   = blockIdx.x >> 2;
    unsigned int rank;
    asm("mov.u32 %0, %%cluster_ctarank;" : "=r"(rank));
    const int t = (int)rank;                 // ci-tile 0..3

    // ---- one-time loads ----
    // W_s[(tap*128+ci)*128 + j_*8 + g*2 + p], col = g*32 + j_*2 + p (thread-contiguous 8)
    for (int idx = tid; idx < 32768; idx += NTHR) {
        int k = idx >> 7, r = idx & 127;
        int tap = k >> 7, ci = k & 127;
        int jj = r >> 3, q = r & 7;
        int g = q >> 1, p = q & 1;
        int co = g * HC + t * 32 + jj * 2 + p;
        W_s[idx] = W_ss[(co * HC + ci) * 3 + tap];
    }
    // WI_s[(tap*3+cn)*128 + j_*8 + g*2 + p]
    for (int idx = tid; idx < 768; idx += NTHR) {
        int k = idx >> 7, r = idx & 127;
        int tap = k / 3, cn = k - tap * 3;
        int jj = r >> 3, q = r & 7;
        int g = q >> 1, p = q & 1;
        int co = g * HC + t * 32 + jj * 2 + p;
        WI_s[idx] = W_is[(co * CIN + cn) * 3 + tap];
    }
    // A0 <- full h0 (all 128 ci), pad row 0 of both buffers zero
    for (int idx = tid; idx < 8192; idx += NTHR) {
        int w = idx >> 7, ci = idx & 127;
        sm[A0_OFF + (w + 1) * AST + ci] = h0[ci * WW + w];
    }
    for (int idx = tid; idx < AST; idx += NTHR) {
        sm[A0_OFF + idx] = 0.f;
        sm[A1_OFF + idx] = 0.f;
    }

    // warp-shaped mapping: 16 warps; each warp spans 4 distinct j_, 8 distinct i5
    const int wid  = tid >> 5;
    const int lane = tid & 31;
    const int j_ = (wid & 3) * 4 + (lane >> 3);     // 0..15
    const int i5 = (wid >> 2) * 8 + (lane & 7);     // 0..31 ; w = wi*32 + i5, wi in {0,1}
    const int j2 = j_ << 1;
    const int j8 = j_ << 3;

    // per-thread persistent state: bias pairs + cell state registers
    unsigned long long bias2[4];
    #pragma unroll
    for (int g = 0; g < 4; g++) {
        int co = g * HC + t * 32 + j2;
        bias2[g] = pack2(b_is[co] + b_ss[co], b_is[co + 1] + b_ss[co + 1]);
    }
    float creg[2][2];
    #pragma unroll
    for (int wi = 0; wi < 2; wi++) {
        int w = wi * 32 + i5;
        creg[wi][0] = c0[(t * 32 + j2) * WW + w];
        creg[wi][1] = c0[(t * 32 + j2 + 1) * WW + w];
    }

    // peer smem base addresses (shared::cluster window) for DSMEM h exchange
    unsigned int mybase;
    asm("{ .reg .u64 a; cvta.to.shared.u64 a, %1; cvt.u32.u64 %0, a; }"
        : "=r"(mybase) : "l"(sm));
    unsigned int peer[CLU];
    #pragma unroll
    for (int r = 0; r < CLU; r++)
        asm("mapa.shared::cluster.u32 %0, %1, %2;" : "=r"(peer[r]) : "r"(mybase), "r"(r));

    __syncthreads();   // local init (W_s, WI_s, A0) visible block-wide

    for (int s = 0; s < HH; s++) {
        const float* Ac = sm + ((s & 1) ? A1_OFF : A0_OFF);
        const unsigned int nextOffB = (unsigned int)(((s & 1) ? A0_OFF : A1_OFF) * 4);

        // ---- acc starts at bias, add x-projection (LDGs overlap following GEMM) ----
        unsigned long long acc[2][4];
        #pragma unroll
        for (int wi = 0; wi < 2; wi++)
            #pragma unroll
            for (int g = 0; g < 4; g++) acc[wi][g] = bias2[g];

        {
            float xr[2][3][2];
            #pragma unroll
            for (int wi = 0; wi < 2; wi++) {
                int w = wi * 32 + i5;
                #pragma unroll
                for (int cn = 0; cn < CIN; cn++) {
                    const float* xb = x + ((b * CIN + cn) * HH + s) * WW;
                    xr[wi][cn][0] = (w > 0) ? xb[w - 1] : 0.f;
                    xr[wi][cn][1] = xb[w];
                }
            }
            #pragma unroll
            for (int tap = 0; tap < 2; tap++)
                #pragma unroll
                for (int cn = 0; cn < CIN; cn++) {
                    const float* wr = WI_s + (tap * 3 + cn) * 128 + j8;
                    ulonglong2 wa  = *(const ulonglong2*)wr;        // gates 0,1
                    ulonglong2 wb2 = *(const ulonglong2*)(wr + 4);  // gates 2,3
                    #pragma unroll
                    for (int wi = 0; wi < 2; wi++) {
                        unsigned long long xp = pack2(xr[wi][cn][tap], xr[wi][cn][tap]);
                        acc[wi][0] = fma2(xp, wa.x,  acc[wi][0]);
                        acc[wi][1] = fma2(xp, wa.y,  acc[wi][1]);
                        acc[wi][2] = fma2(xp, wb2.x, acc[wi][2]);
                        acc[wi][3] = fma2(xp, wb2.y, acc[wi][3]);
                    }
                }
        }

        // ---- GEMM: (2 w) x (4 gates x 2 ci) over K = 2 taps x 128 ci ----
        for (int cb = 0; cb < HC; cb += 4) {
            float4 aL4[2], aC4[2];
            #pragma unroll
            for (int wi = 0; wi < 2; wi++) {
                int wp = wi * 32 + i5;
                aL4[wi] = *(const float4*)(Ac + wp * AST + cb);
                aC4[wi] = *(const float4*)(Ac + (wp + 1) * AST + cb);
            }
            #pragma unroll
            for (int u = 0; u < 4; u++) {
                const float* wr0 = W_s + (cb + u) * 128 + j8;
                const float* wr1 = wr0 + 128 * 128;
                ulonglong2 w0a = *(const ulonglong2*)wr0;        // tap0 gates 0,1
                ulonglong2 w0b = *(const ulonglong2*)(wr0 + 4);  // tap0 gates 2,3
                ulonglong2 w1a = *(const ulonglong2*)wr1;        // tap1 gates 0,1
                ulonglong2 w1b = *(const ulonglong2*)(wr1 + 4);  // tap1 gates 2,3
                #pragma unroll
                for (int wi = 0; wi < 2; wi++) {
                    float aL = ((const float*)&aL4[wi])[u];
                    float aC = ((const float*)&aC4[wi])[u];
                    unsigned long long aLp = pack2(aL, aL);
                    unsigned long long aCp = pack2(aC, aC);
                    acc[wi][0] = fma2(aLp, w0a.x, acc[wi][0]);
                    acc[wi][1] = fma2(aLp, w0a.y, acc[wi][1]);
                    acc[wi][2] = fma2(aLp, w0b.x, acc[wi][2]);
                    acc[wi][3] = fma2(aLp, w0b.y, acc[wi][3]);
                    acc[wi][0] = fma2(aCp, w1a.x, acc[wi][0]);
                    acc[wi][1] = fma2(aCp, w1a.y, acc[wi][1]);
                    acc[wi][2] = fma2(aCp, w1b.x, acc[wi][2]);
                    acc[wi][3] = fma2(aCp, w1b.y, acc[wi][3]);
                }
            }
        }

        // ---- gates -> c,h in registers; write out + h to all 4 cluster CTAs ----
        #pragma unroll
        for (int wi = 0; wi < 2; wi++) {
            int w = wi * 32 + i5;
            float gv[4][2];
            #pragma unroll
            for (int g = 0; g < 4; g++) {
                float a0, a1;
                unpack2(acc[wi][g], a0, a1);
                gv[g][0] = sigm(a0);
                gv[g][1] = sigm(a1);
            }
            float hp[2];
            #pragma unroll
            for (int p = 0; p < 2; p++) {
                float cn2 = gv[1][p] * creg[wi][p] + gv[2][p] * gv[3][p];
                creg[wi][p] = cn2;
                float h = gv[0][p] * tanhf(cn2);
                hp[p] = h;
                out[((b * HC + t * 32 + j2 + p) * HH + s) * WW + w] = h;
            }
            unsigned long long hpair = pack2(hp[0], hp[1]);
            unsigned int off = nextOffB + (unsigned int)(((w + 1) * AST + t * 32 + j2) * 4);
            #pragma unroll
            for (int r = 0; r < CLU; r++)
                asm volatile("st.shared::cluster.b64 [%0], %1;"
                             :: "r"(peer[r] + off), "l"(hpair) : "memory");
        }

        // one cluster barrier per step: h(s) visible in everyone's A_next
        asm volatile("barrier.cluster.arrive.aligned;" ::: "memory");
        asm volatile("barrier.cluster.wait.aligned;" ::: "memory");
    }
}

extern "C" void kernel_launch(void* const* d_in, const int* in_sizes, int n_in,
                              void* d_out, int out_size) {
    const float* x    = (const float*)d_in[0];
    const float* W_is = (const float*)d_in[1];
    const float* b_is = (const float*)d_in[2];
    const float* W_ss = (const float*)d_in[3];
    const float* b_ss = (const float*)d_in[4];
    const float* h0   = (const float*)d_in[5];
    const float* c0   = (const float*)d_in[6];
    float* out = (float*)d_out;

    size_t smem = (size_t)SMEM_FLOATS * sizeof(float);
    cudaFuncSetAttribute(rowlstm_kernel,
                         cudaFuncAttributeMaxDynamicSharedMemorySize, (int)smem);
    rowlstm_kernel<<<NCTA, NTHR, smem>>>(x, W_is, b_is, W_ss, b_ss, h0, c0, out);
}

// round 11
// speedup vs baseline: 1.4085x; 1.4081x over previous
#include <cuda_runtime.h>
#include <cstdint>

#define CIN   3
#define HH    64
#define WW    64
#define HC    128
#define NCTA  128
#define NTHR  256
#define CLU   4
#define KD    256
#define RST   260                 // padded row stride (floats): conflict-free frag loads

// smem byte offsets
#define WI_OFF 0                  // 7*128 floats = 3584 B
#define A_OFF  3584               // 64 x RST floats = 66560 B
#define B_OFF  70144              // 128 x RST tf32  = 133120 B
#define SMEM_BYTES 203264

__device__ __forceinline__ unsigned smem_u32(const void* p) {
    unsigned a;
    asm("{ .reg .u64 t; cvta.to.shared.u64 t, %1; cvt.u32.u64 %0, t; }" : "=r"(a) : "l"(p));
    return a;
}
__device__ __forceinline__ float sigm(float v) { return 1.f / (1.f + __expf(-v)); }

// round-to-nearest tf32 hi + fp32 residual lo (lo low bits truncated by HMMA, ~2^-22)
__device__ __forceinline__ void tf32split(float a, unsigned& hi, unsigned& lo) {
    unsigned u = __float_as_uint(a);
    unsigned h = (u + 0x1000u) & 0xFFFFE000u;
    hi = h;
    lo = __float_as_uint(a - __uint_as_float(h));
}

#define MMA(c0_,c1_,c2_,c3_,a0_,a1_,a2_,a3_,b0_,b1_) \
    asm volatile("mma.sync.aligned.m16n8k8.row.col.f32.tf32.tf32.f32 " \
        "{%0,%1,%2,%3}, {%4,%5,%6,%7}, {%8,%9}, {%0,%1,%2,%3};" \
        : "+f"(c0_), "+f"(c1_), "+f"(c2_), "+f"(c3_) \
        : "r"(a0_), "r"(a1_), "r"(a2_), "r"(a3_), "r"(b0_), "r"(b1_))

__global__ __launch_bounds__(NTHR, 1) __cluster_dims__(CLU, 1, 1)
void rowlstm_kernel(const float* __restrict__ x,
                    const float* __restrict__ W_is,
                    const float* __restrict__ b_is,
                    const float* __restrict__ W_ss,
                    const float* __restrict__ b_ss,
                    const float* __restrict__ h0,
                    const float* __restrict__ c0,
                    float* __restrict__ out)
{
    extern __shared__ char smc[];
    float*    WIs = (float*)(smc + WI_OFF);
    float*    As  = (float*)(smc + A_OFF);
    unsigned* Bsm = (unsigned*)(smc + B_OFF);

    const int tid = threadIdx.x, wid = tid >> 5, lane = tid & 31;
    const int b = blockIdx.x >> 2;
    unsigned rank; asm("mov.u32 %0, %%cluster_ctarank;" : "=r"(rank));
    const int t = (int)rank;
    const unsigned sb = smem_u32(smc);

    // ---- one-time fills ----
    // n -> (gate, ci_local): g = bit0 + 2*bit3 ; cil = bits[1:2] + 4*bit4 + 8*bits[5:6]
    for (int idx = tid; idx < HC * KD; idx += NTHR) {
        int n = idx >> 8, k = idx & 255;
        int tap = k >> 7, ci = k & 127;
        int g   = (n & 1) | (((n >> 3) & 1) << 1);
        int cil = ((n >> 1) & 3) | (((n >> 4) & 1) << 2) | (((n >> 5) & 3) << 3);
        int co  = g * HC + t * 32 + cil;
        unsigned u = __float_as_uint(W_ss[(co * HC + ci) * 3 + tap]);
        Bsm[n * RST + k] = (u + 0x1000u) & 0xFFFFE000u;       // tf32-rounded weights
    }
    for (int idx = tid; idx < 7 * 128; idx += NTHR) {
        int row = idx >> 7, n = idx & 127;
        int g   = (n & 1) | (((n >> 3) & 1) << 1);
        int cil = ((n >> 1) & 3) | (((n >> 4) & 1) << 2) | (((n >> 5) & 3) << 3);
        int co  = g * HC + t * 32 + cil;
        float v;
        if (row < 6) { int tap = row / 3, cn = row - tap * 3; v = W_is[(co * CIN + cn) * 3 + tap]; }
        else v = b_is[co] + b_ss[co];
        WIs[row * 128 + n] = v;
    }
    // A: k<128 left tap h[w-1] (row0 = 0), k>=128 center tap h[w]
    for (int idx = tid; idx < 64 * KD; idx += NTHR) {
        int r = idx >> 8, c = idx & 255;
        As[r * RST + c] = (c < 128) ? ((r > 0) ? h0[c * WW + (r - 1)] : 0.f)
                                    : h0[(c - 128) * WW + r];
    }
    __syncthreads();

    const int warp_m = wid >> 2, warp_n = wid & 3;
    const int m0 = warp_m * 32, n0 = warp_n * 32;
    const int r4 = lane >> 2, c4 = lane & 3;

    float creg[2][2][2];
    #pragma unroll
    for (int m = 0; m < 2; m++)
        #pragma unroll
        for (int rs = 0; rs < 2; rs++)
            #pragma unroll
            for (int cs = 0; cs < 2; cs++) {
                int w   = m0 + m * 16 + rs * 8 + r4;
                int cig = t * 32 + c4 + warp_n * 8 + 4 * cs;
                creg[m][rs][cs] = c0[cig * WW + w];
            }

    unsigned peer[CLU];
    #pragma unroll
    for (int r = 0; r < CLU; r++)
        asm("mapa.shared::cluster.u32 %0, %1, %2;" : "=r"(peer[r]) : "r"(sb), "r"(r));

    asm volatile("barrier.cluster.arrive.aligned;" ::: "memory");  // A(0) ready (mine)

    for (int s = 0; s < HH; s++) {
        // ---- acc init = bias + x-projection (no A dependency: before the wait) ----
        float xv[2][2][6];
        #pragma unroll
        for (int m = 0; m < 2; m++)
            #pragma unroll
            for (int rs = 0; rs < 2; rs++) {
                int w = m0 + m * 16 + rs * 8 + r4;
                #pragma unroll
                for (int cn = 0; cn < CIN; cn++) {
                    const float* xb = x + ((b * CIN + cn) * HH + s) * WW;
                    xv[m][rs][cn]     = (w > 0) ? xb[w - 1] : 0.f;
                    xv[m][rs][3 + cn] = xb[w];
                }
            }
        float acc[2][4][4];
        #pragma unroll
        for (int n8 = 0; n8 < 4; n8++)
            #pragma unroll
            for (int pq = 0; pq < 2; pq++) {
                int ncol = n0 + n8 * 8 + 2 * c4 + pq;
                float wib = WIs[6 * 128 + ncol];
                float wir[6];
                #pragma unroll
                for (int rr = 0; rr < 6; rr++) wir[rr] = WIs[rr * 128 + ncol];
                #pragma unroll
                for (int m = 0; m < 2; m++)
                    #pragma unroll
                    for (int rs = 0; rs < 2; rs++) {
                        float v = wib;
                        #pragma unroll
                        for (int rr = 0; rr < 6; rr++) v += xv[m][rs][rr] * wir[rr];
                        acc[m][n8][pq + 2 * rs] = v;
                    }
            }

        asm volatile("barrier.cluster.wait.aligned;" ::: "memory");   // A(s) ready cluster-wide

        // ---- GEMM: 32 k8-steps, split-A tf32 HMMA ----
        #pragma unroll 4
        for (int ks = 0; ks < 32; ks++) {
            int k0 = ks * 8;
            unsigned ahi[2][4], alo[2][4];
            #pragma unroll
            for (int m = 0; m < 2; m++) {
                const float* ab = As + (m0 + m * 16 + r4) * RST + k0 + c4;
                tf32split(ab[0],           ahi[m][0], alo[m][0]);   // (r,   k)
                tf32split(ab[8 * RST],     ahi[m][1], alo[m][1]);   // (r+8, k)
                tf32split(ab[4],           ahi[m][2], alo[m][2]);   // (r,   k+4)
                tf32split(ab[8 * RST + 4], ahi[m][3], alo[m][3]);   // (r+8, k+4)
            }
            unsigned bf[4][2];
            const unsigned* bb = Bsm + (n0 + r4) * RST + k0 + c4;
            #pragma unroll
            for (int n8 = 0; n8 < 4; n8++) {
                bf[n8][0] = bb[n8 * 8 * RST];        // (k,   n)
                bf[n8][1] = bb[n8 * 8 * RST + 4];    // (k+4, n)
            }
            #pragma unroll
            for (int m = 0; m < 2; m++)
                #pragma unroll
                for (int n8 = 0; n8 < 4; n8++) {
                    MMA(acc[m][n8][0], acc[m][n8][1], acc[m][n8][2], acc[m][n8][3],
                        ahi[m][0], ahi[m][1], ahi[m][2], ahi[m][3], bf[n8][0], bf[n8][1]);
                    MMA(acc[m][n8][0], acc[m][n8][1], acc[m][n8][2], acc[m][n8][3],
                        alo[m][0], alo[m][1], alo[m][2], alo[m][3], bf[n8][0], bf[n8][1]);
                }
        }
        asm volatile("barrier.cluster.arrive.aligned;" ::: "memory"); // done reading A(s)

        // ---- epilogue: gates -> c,h ----
        float hv[2][2][2];
        #pragma unroll
        for (int m = 0; m < 2; m++)
            #pragma unroll
            for (int rs = 0; rs < 2; rs++)
                #pragma unroll
                for (int cs = 0; cs < 2; cs++) {
                    float o  = sigm(acc[m][2 * cs][2 * rs]);
                    float f  = sigm(acc[m][2 * cs][2 * rs + 1]);
                    float ii = sigm(acc[m][2 * cs + 1][2 * rs]);
                    float gg = sigm(acc[m][2 * cs + 1][2 * rs + 1]);
                    float cc = f * creg[m][rs][cs] + ii * gg;
                    creg[m][rs][cs] = cc;
                    float h = o * tanhf(cc);
                    hv[m][rs][cs] = h;
                    int w   = m0 + m * 16 + rs * 8 + r4;
                    int cig = t * 32 + c4 + warp_n * 8 + 4 * cs;
                    out[((b * HC + cig) * HH + s) * WW + w] = h;
                }

        asm volatile("barrier.cluster.wait.aligned;" ::: "memory");   // everyone done reading

        #pragma unroll
        for (int m = 0; m < 2; m++)
            #pragma unroll
            for (int rs = 0; rs < 2; rs++)
                #pragma unroll
                for (int cs = 0; cs < 2; cs++) {
                    int w   = m0 + m * 16 + rs * 8 + r4;
                    int cig = t * 32 + c4 + warp_n * 8 + 4 * cs;
                    unsigned hb = __float_as_uint(hv[m][rs][cs]);
                    unsigned coff = (unsigned)(A_OFF + (w * RST + 128 + cig) * 4);
                    #pragma unroll
                    for (int r = 0; r < CLU; r++)
                        asm volatile("st.shared::cluster.b32 [%0], %1;"
                                     :: "r"(peer[r] + coff), "r"(hb) : "memory");
                    if (w < 63) {
                        unsigned loff = (unsigned)(A_OFF + ((w + 1) * RST + cig) * 4);
                        #pragma unroll
                        for (int r = 0; r < CLU; r++)
                            asm volatile("st.shared::cluster.b32 [%0], %1;"
                                         :: "r"(peer[r] + loff), "r"(hb) : "memory");
                    }
                }
        asm volatile("barrier.cluster.arrive.aligned;" ::: "memory"); // A(s+1) ready
    }
    asm volatile("barrier.cluster.wait.aligned;" ::: "memory");       // close final phase
}

extern "C" void kernel_launch(void* const* d_in, const int* in_sizes, int n_in,
                              void* d_out, int out_size) {
    const float* x    = (const float*)d_in[0];
    const float* W_is = (const float*)d_in[1];
    const float* b_is = (const float*)d_in[2];
    const float* W_ss = (const float*)d_in[3];
    const float* b_ss = (const float*)d_in[4];
    const float* h0   = (const float*)d_in[5];
    const float* c0   = (const float*)d_in[6];
    float* out = (float*)d_out;

    cudaFuncSetAttribute(rowlstm_kernel,
                         cudaFuncAttributeMaxDynamicSharedMemorySize, SMEM_BYTES);
    rowlstm_kernel<<<NCTA, NTHR, SMEM_BYTES>>>(x, W_is, b_is, W_ss, b_ss, h0, c0, out);
}

// round 13
// speedup vs baseline: 1.6256x; 1.1541x over previous
#include <cuda_runtime.h>
#include <cstdint>

#define CIN   3
#define HH    64
#define WW    64
#define HC    128
#define NCTA  128
#define NTHR  256
#define CLU   4
#define AST   132                 // A row stride (floats)
#define BST   260                 // B row stride (floats)

// smem byte offsets
#define WI_OFF 0                  // 7*128 floats = 3584 B
#define A0_OFF 3584               // 65 x AST floats = 34320 B
#define A1_OFF 37904
#define B_OFF  72224              // 128 x BST tf32 = 133120 B
#define SMEM_BYTES 205344

__device__ __forceinline__ unsigned smem_u32(const void* p) {
    unsigned a;
    asm("{ .reg .u64 t; cvta.to.shared.u64 t, %1; cvt.u32.u64 %0, t; }" : "=r"(a) : "l"(p));
    return a;
}
__device__ __forceinline__ float sigm(float v) { return 1.f / (1.f + __expf(-v)); }

// round-to-nearest tf32 hi + fp32 residual lo
__device__ __forceinline__ void tf32split(float a, unsigned& hi, unsigned& lo) {
    unsigned u = __float_as_uint(a);
    unsigned h = (u + 0x1000u) & 0xFFFFE000u;
    hi = h;
    lo = __float_as_uint(a - __uint_as_float(h));
}

#define MMA(c0_,c1_,c2_,c3_,a0_,a1_,a2_,a3_,b0_,b1_) \
    asm volatile("mma.sync.aligned.m16n8k8.row.col.f32.tf32.tf32.f32 " \
        "{%0,%1,%2,%3}, {%4,%5,%6,%7}, {%8,%9}, {%0,%1,%2,%3};" \
        : "+f"(c0_), "+f"(c1_), "+f"(c2_), "+f"(c3_) \
        : "r"(a0_), "r"(a1_), "r"(a2_), "r"(a3_), "r"(b0_), "r"(b1_))

__global__ __launch_bounds__(NTHR, 1) __cluster_dims__(CLU, 1, 1)
void rowlstm_kernel(const float* __restrict__ x,
                    const float* __restrict__ W_is,
                    const float* __restrict__ b_is,
                    const float* __restrict__ W_ss,
                    const float* __restrict__ b_ss,
                    const float* __restrict__ h0,
                    const float* __restrict__ c0,
                    float* __restrict__ out)
{
    extern __shared__ char smc[];
    float*    WIs = (float*)(smc + WI_OFF);
    unsigned* Bsm = (unsigned*)(smc + B_OFF);

    const int tid = threadIdx.x, wid = tid >> 5, lane = tid & 31;
    const int b = blockIdx.x >> 2;
    unsigned rank; asm("mov.u32 %0, %%cluster_ctarank;" : "=r"(rank));
    const int t = (int)rank;
    const unsigned sb = smem_u32(smc);

    // ---- one-time fills ----
    // B[n][k]: k = tap*128 + ci, tf32-rounded weights
    // n -> (gate, ci_local): g = bit0 + 2*bit3 ; cil = bits[1:2] + 4*bit4 + 8*bits[5:6]
    for (int idx = tid; idx < HC * 256; idx += NTHR) {
        int n = idx >> 8, k = idx & 255;
        int tap = k >> 7, ci = k & 127;
        int g   = (n & 1) | (((n >> 3) & 1) << 1);
        int cil = ((n >> 1) & 3) | (((n >> 4) & 1) << 2) | (((n >> 5) & 3) << 3);
        int co  = g * HC + t * 32 + cil;
        unsigned u = __float_as_uint(W_ss[(co * HC + ci) * 3 + tap]);
        Bsm[n * BST + k] = (u + 0x1000u) & 0xFFFFE000u;
    }
    for (int idx = tid; idx < 7 * 128; idx += NTHR) {
        int row = idx >> 7, n = idx & 127;
        int g   = (n & 1) | (((n >> 3) & 1) << 1);
        int cil = ((n >> 1) & 3) | (((n >> 4) & 1) << 2) | (((n >> 5) & 3) << 3);
        int co  = g * HC + t * 32 + cil;
        float v;
        if (row < 6) { int tap = row / 3, cn = row - tap * 3; v = W_is[(co * CIN + cn) * 3 + tap]; }
        else v = b_is[co] + b_ss[co];
        WIs[row * 128 + n] = v;
    }
    // A buffers: h[w] at row w+1; row 0 = zeros (both buffers)
    for (int idx = tid; idx < 64 * 128; idx += NTHR) {
        int w = idx >> 7, ci = idx & 127;
        ((float*)(smc + A0_OFF))[(w + 1) * AST + ci] = h0[ci * WW + w];
    }
    for (int idx = tid; idx < 128; idx += NTHR) {
        ((float*)(smc + A0_OFF))[idx] = 0.f;
        ((float*)(smc + A1_OFF))[idx] = 0.f;
    }
    __syncthreads();

    const int warp_m = wid >> 2, warp_n = wid & 3;
    const int m0 = warp_m * 32, n0 = warp_n * 32;
    const int r4 = lane >> 2, c4 = lane & 3;

    float creg[2][2][2];
    #pragma unroll
    for (int m = 0; m < 2; m++)
        #pragma unroll
        for (int rs = 0; rs < 2; rs++)
            #pragma unroll
            for (int cs = 0; cs < 2; cs++) {
                int w   = m0 + m * 16 + rs * 8 + r4;
                int cig = t * 32 + c4 + warp_n * 8 + 4 * cs;
                creg[m][rs][cs] = c0[cig * WW + w];
            }

    unsigned peer[CLU];
    #pragma unroll
    for (int r = 0; r < CLU; r++)
        asm("mapa.shared::cluster.u32 %0, %1, %2;" : "=r"(peer[r]) : "r"(sb), "r"(r));

    // prologue cluster sync: everyone's smem initialized before cross-CTA writes
    asm volatile("barrier.cluster.arrive.aligned;" ::: "memory");
    asm volatile("barrier.cluster.wait.aligned;" ::: "memory");

    for (int s = 0; s < HH; s++) {
        const float*   Ac   = (const float*)(smc + ((s & 1) ? A1_OFF : A0_OFF));
        float*         An   = (float*)      (smc + ((s & 1) ? A0_OFF : A1_OFF));
        const unsigned AnB  = (unsigned)((s & 1) ? A0_OFF : A1_OFF);

        // ---- acc init = bias + x-projection ----
        float xv[2][2][6];
        #pragma unroll
        for (int m = 0; m < 2; m++)
            #pragma unroll
            for (int rs = 0; rs < 2; rs++) {
                int w = m0 + m * 16 + rs * 8 + r4;
                #pragma unroll
                for (int cn = 0; cn < CIN; cn++) {
                    const float* xb = x + ((b * CIN + cn) * HH + s) * WW;
                    xv[m][rs][cn]     = (w > 0) ? xb[w - 1] : 0.f;
                    xv[m][rs][3 + cn] = xb[w];
                }
            }
        float acc[2][4][4];
        #pragma unroll
        for (int n8 = 0; n8 < 4; n8++)
            #pragma unroll
            for (int pq = 0; pq < 2; pq++) {
                int ncol = n0 + n8 * 8 + 2 * c4 + pq;
                float wib = WIs[6 * 128 + ncol];
                float wir[6];
                #pragma unroll
                for (int rr = 0; rr < 6; rr++) wir[rr] = WIs[rr * 128 + ncol];
                #pragma unroll
                for (int m = 0; m < 2; m++)
                    #pragma unroll
                    for (int rs = 0; rs < 2; rs++) {
                        float v = wib;
                        #pragma unroll
                        for (int rr = 0; rr < 6; rr++) v += xv[m][rs][rr] * wir[rr];
                        acc[m][n8][pq + 2 * rs] = v;
                    }
            }

        // ---- GEMM: 32 k8-steps (16 left-tap rows w, 16 center-tap rows w+1) ----
        #pragma unroll 4
        for (int ks = 0; ks < 32; ks++) {
            int tap = ks >> 4;
            int kc  = (ks & 15) * 8;
            unsigned ahi[2][4], alo[2][4];
            #pragma unroll
            for (int m = 0; m < 2; m++) {
                const float* ab = Ac + (m0 + m * 16 + r4 + tap) * AST + kc + c4;
                tf32split(ab[0],           ahi[m][0], alo[m][0]);
                tf32split(ab[8 * AST],     ahi[m][1], alo[m][1]);
                tf32split(ab[4],           ahi[m][2], alo[m][2]);
                tf32split(ab[8 * AST + 4], ahi[m][3], alo[m][3]);
            }
            unsigned bf[4][2];
            const unsigned* bb = Bsm + (n0 + r4) * BST + tap * 128 + kc + c4;
            #pragma unroll
            for (int n8 = 0; n8 < 4; n8++) {
                bf[n8][0] = bb[n8 * 8 * BST];
                bf[n8][1] = bb[n8 * 8 * BST + 4];
            }
            #pragma unroll
            for (int m = 0; m < 2; m++)
                #pragma unroll
                for (int n8 = 0; n8 < 4; n8++) {
                    MMA(acc[m][n8][0], acc[m][n8][1], acc[m][n8][2], acc[m][n8][3],
                        ahi[m][0], ahi[m][1], ahi[m][2], ahi[m][3], bf[n8][0], bf[n8][1]);
                    MMA(acc[m][n8][0], acc[m][n8][1], acc[m][n8][2], acc[m][n8][3],
                        alo[m][0], alo[m][1], alo[m][2], alo[m][3], bf[n8][0], bf[n8][1]);
                }
        }

        // ---- epilogue: gates -> c,h; out + local stage into An (own slice) ----
        #pragma unroll
        for (int m = 0; m < 2; m++)
            #pragma unroll
            for (int rs = 0; rs < 2; rs++)
                #pragma unroll
                for (int cs = 0; cs < 2; cs++) {
                    float o  = sigm(acc[m][2 * cs][2 * rs]);
                    float f  = sigm(acc[m][2 * cs][2 * rs + 1]);
                    float ii = sigm(acc[m][2 * cs + 1][2 * rs]);
                    float gg = sigm(acc[m][2 * cs + 1][2 * rs + 1]);
                    float cc = f * creg[m][rs][cs] + ii * gg;
                    creg[m][rs][cs] = cc;
                    float h = o * tanhf(cc);
                    int w   = m0 + m * 16 + rs * 8 + r4;
                    int cig = t * 32 + c4 + warp_n * 8 + 4 * cs;
                    out[((b * HC + cig) * HH + s) * WW + w] = h;
                    An[(w + 1) * AST + cig] = h;
                }
        __syncthreads();   // own An slice staged

        // ---- broadcast own 32-ci slice (rows 1..64) to the 3 peers, b64 ----
        for (int idx = tid; idx < 1024; idx += NTHR) {
            int row = (idx >> 4) + 1;
            int cp  = (idx & 15) << 1;
            unsigned off = AnB + (unsigned)((row * AST + t * 32 + cp) * 4);
            unsigned long long v = *(const unsigned long long*)(smc + off);
            #pragma unroll
            for (int r = 0; r < CLU; r++)
                if (r != t)
                    asm volatile("st.shared::cluster.b64 [%0], %1;"
                                 :: "r"(peer[r] + off), "l"(v) : "memory");
        }

        // single cluster barrier per step: A(s+1) complete everywhere
        asm volatile("barrier.cluster.arrive.aligned;" ::: "memory");
        asm volatile("barrier.cluster.wait.aligned;" ::: "memory");
    }
}

extern "C" void kernel_launch(void* const* d_in, const int* in_sizes, int n_in,
                              void* d_out, int out_size) {
    const float* x    = (const float*)d_in[0];
    const float* W_is = (const float*)d_in[1];
    const float* b_is = (const float*)d_in[2];
    const float* W_ss = (const float*)d_in[3];
    const float* b_ss = (const float*)d_in[4];
    const float* h0   = (const float*)d_in[5];
    const float* c0   = (const float*)d_in[6];
    float* out = (float*)d_out;

    cudaFuncSetAttribute(rowlstm_kernel,
                         cudaFuncAttributeMaxDynamicSharedMemorySize, SMEM_BYTES);
    rowlstm_kernel<<<NCTA, NTHR, SMEM_BYTES>>>(x, W_is, b_is, W_ss, b_ss, h0, c0, out);
}

// round 14
// speedup vs baseline: 1.7698x; 1.0888x over previous
#include <cuda_runtime.h>
#include <cstdint>

#define CIN   3
#define HH    64
#define WW    64
#define HC    128
#define NCTA  128
#define NTHR  512
#define CLU   4
#define AST   132                 // A row stride (floats)
#define BST   260                 // B row stride (floats)

// smem byte offsets
#define WI_OFF 0                  // 7*128 floats = 3584 B
#define A0_OFF 3584               // 65 x AST floats = 34320 B
#define A1_OFF 37904
#define B_OFF  72224              // 128 x BST tf32 = 133120 B
#define SMEM_BYTES 205344

__device__ __forceinline__ unsigned smem_u32(const void* p) {
    unsigned a;
    asm("{ .reg .u64 t; cvta.to.shared.u64 t, %1; cvt.u32.u64 %0, t; }" : "=r"(a) : "l"(p));
    return a;
}
__device__ __forceinline__ float sigm(float v) { return 1.f / (1.f + __expf(-v)); }

// round-to-nearest tf32 hi + fp32 residual lo
__device__ __forceinline__ void tf32split(float a, unsigned& hi, unsigned& lo) {
    unsigned u = __float_as_uint(a);
    unsigned h = (u + 0x1000u) & 0xFFFFE000u;
    hi = h;
    lo = __float_as_uint(a - __uint_as_float(h));
}

#define MMA(c0_,c1_,c2_,c3_,a0_,a1_,a2_,a3_,b0_,b1_) \
    asm volatile("mma.sync.aligned.m16n8k8.row.col.f32.tf32.tf32.f32 " \
        "{%0,%1,%2,%3}, {%4,%5,%6,%7}, {%8,%9}, {%0,%1,%2,%3};" \
        : "+f"(c0_), "+f"(c1_), "+f"(c2_), "+f"(c3_) \
        : "r"(a0_), "r"(a1_), "r"(a2_), "r"(a3_), "r"(b0_), "r"(b1_))

__global__ __launch_bounds__(NTHR, 1) __cluster_dims__(CLU, 1, 1)
void rowlstm_kernel(const float* __restrict__ x,
                    const float* __restrict__ W_is,
                    const float* __restrict__ b_is,
                    const float* __restrict__ W_ss,
                    const float* __restrict__ b_ss,
                    const float* __restrict__ h0,
                    const float* __restrict__ c0,
                    float* __restrict__ out)
{
    extern __shared__ char smc[];
    float*    WIs = (float*)(smc + WI_OFF);
    unsigned* Bsm = (unsigned*)(smc + B_OFF);

    const int tid = threadIdx.x, wid = tid >> 5, lane = tid & 31;
    const int b = blockIdx.x >> 2;
    unsigned rank; asm("mov.u32 %0, %%cluster_ctarank;" : "=r"(rank));
    const int t = (int)rank;
    const unsigned sb = smem_u32(smc);

    // ---- one-time fills ----
    // B[n][k]: k = tap*128 + ci, tf32-rounded weights
    // n -> (gate, ci_local): g = bit0 + 2*bit3 ; cil = bits[1:2] + 4*bit4 + 8*bits[5:6]
    for (int idx = tid; idx < HC * 256; idx += NTHR) {
        int n = idx >> 8, k = idx & 255;
        int tap = k >> 7, ci = k & 127;
        int g   = (n & 1) | (((n >> 3) & 1) << 1);
        int cil = ((n >> 1) & 3) | (((n >> 4) & 1) << 2) | (((n >> 5) & 3) << 3);
        int co  = g * HC + t * 32 + cil;
        unsigned u = __float_as_uint(W_ss[(co * HC + ci) * 3 + tap]);
        Bsm[n * BST + k] = (u + 0x1000u) & 0xFFFFE000u;
    }
    for (int idx = tid; idx < 7 * 128; idx += NTHR) {
        int row = idx >> 7, n = idx & 127;
        int g   = (n & 1) | (((n >> 3) & 1) << 1);
        int cil = ((n >> 1) & 3) | (((n >> 4) & 1) << 2) | (((n >> 5) & 3) << 3);
        int co  = g * HC + t * 32 + cil;
        float v;
        if (row < 6) { int tap = row / 3, cn = row - tap * 3; v = W_is[(co * CIN + cn) * 3 + tap]; }
        else v = b_is[co] + b_ss[co];
        WIs[row * 128 + n] = v;
    }
    // A buffers: h[w] at row w+1; row 0 = zeros (both buffers)
    for (int idx = tid; idx < 64 * 128; idx += NTHR) {
        int w = idx >> 7, ci = idx & 127;
        ((float*)(smc + A0_OFF))[(w + 1) * AST + ci] = h0[ci * WW + w];
    }
    for (int idx = tid; idx < 128; idx += NTHR) {
        ((float*)(smc + A0_OFF))[idx] = 0.f;
        ((float*)(smc + A1_OFF))[idx] = 0.f;
    }
    __syncthreads();

    // 16 warps: warp tile M=16 (warp_m 0..3), N=32 (warp_n 0..3)
    const int warp_m = wid >> 2, warp_n = wid & 3;
    const int m0 = warp_m * 16, n0 = warp_n * 32;
    const int r4 = lane >> 2, c4 = lane & 3;

    float creg[2][2];
    #pragma unroll
    for (int rs = 0; rs < 2; rs++)
        #pragma unroll
        for (int cs = 0; cs < 2; cs++) {
            int w   = m0 + rs * 8 + r4;
            int cig = t * 32 + c4 + warp_n * 8 + 4 * cs;
            creg[rs][cs] = c0[cig * WW + w];
        }

    unsigned peer[CLU];
    #pragma unroll
    for (int r = 0; r < CLU; r++)
        asm("mapa.shared::cluster.u32 %0, %1, %2;" : "=r"(peer[r]) : "r"(sb), "r"(r));

    // prologue cluster sync
    asm volatile("barrier.cluster.arrive.aligned;" ::: "memory");
    asm volatile("barrier.cluster.wait.aligned;" ::: "memory");

    for (int s = 0; s < HH; s++) {
        const float*   Ac  = (const float*)(smc + ((s & 1) ? A1_OFF : A0_OFF));
        float*         An  = (float*)      (smc + ((s & 1) ? A0_OFF : A1_OFF));
        const unsigned AnB = (unsigned)((s & 1) ? A0_OFF : A1_OFF);

        // ---- acc init = bias + x-projection ----
        float xv[2][6];
        #pragma unroll
        for (int rs = 0; rs < 2; rs++) {
            int w = m0 + rs * 8 + r4;
            #pragma unroll
            for (int cn = 0; cn < CIN; cn++) {
                const float* xb = x + ((b * CIN + cn) * HH + s) * WW;
                xv[rs][cn]     = (w > 0) ? xb[w - 1] : 0.f;
                xv[rs][3 + cn] = xb[w];
            }
        }
        float acc[4][4];
        #pragma unroll
        for (int n8 = 0; n8 < 4; n8++)
            #pragma unroll
            for (int pq = 0; pq < 2; pq++) {
                int ncol = n0 + n8 * 8 + 2 * c4 + pq;
                float wib = WIs[6 * 128 + ncol];
                float wir[6];
                #pragma unroll
                for (int rr = 0; rr < 6; rr++) wir[rr] = WIs[rr * 128 + ncol];
                #pragma unroll
                for (int rs = 0; rs < 2; rs++) {
                    float v = wib;
                    #pragma unroll
                    for (int rr = 0; rr < 6; rr++) v += xv[rs][rr] * wir[rr];
                    acc[n8][pq + 2 * rs] = v;
                }
            }

        // ---- GEMM: 32 k8-steps (16 left-tap rows w, 16 center-tap rows w+1) ----
        #pragma unroll 4
        for (int ks = 0; ks < 32; ks++) {
            int tap = ks >> 4;
            int kc  = (ks & 15) * 8;
            unsigned ahi[4], alo[4];
            {
                const float* ab = Ac + (m0 + r4 + tap) * AST + kc + c4;
                tf32split(ab[0],           ahi[0], alo[0]);
                tf32split(ab[8 * AST],     ahi[1], alo[1]);
                tf32split(ab[4],           ahi[2], alo[2]);
                tf32split(ab[8 * AST + 4], ahi[3], alo[3]);
            }
            unsigned bf[4][2];
            const unsigned* bb = Bsm + (n0 + r4) * BST + tap * 128 + kc + c4;
            #pragma unroll
            for (int n8 = 0; n8 < 4; n8++) {
                bf[n8][0] = bb[n8 * 8 * BST];
                bf[n8][1] = bb[n8 * 8 * BST + 4];
            }
            #pragma unroll
            for (int n8 = 0; n8 < 4; n8++) {
                MMA(acc[n8][0], acc[n8][1], acc[n8][2], acc[n8][3],
                    ahi[0], ahi[1], ahi[2], ahi[3], bf[n8][0], bf[n8][1]);
                MMA(acc[n8][0], acc[n8][1], acc[n8][2], acc[n8][3],
                    alo[0], alo[1], alo[2], alo[3], bf[n8][0], bf[n8][1]);
            }
        }

        // ---- epilogue: gates -> c,h; out + local stage into An (own slice) ----
        #pragma unroll
        for (int rs = 0; rs < 2; rs++)
            #pragma unroll
            for (int cs = 0; cs < 2; cs++) {
                float o  = sigm(acc[2 * cs][2 * rs]);
                float f  = sigm(acc[2 * cs][2 * rs + 1]);
                float ii = sigm(acc[2 * cs + 1][2 * rs]);
                float gg = sigm(acc[2 * cs + 1][2 * rs + 1]);
                float cc = f * creg[rs][cs] + ii * gg;
                creg[rs][cs] = cc;
                float h = o * tanhf(cc);
                int w   = m0 + rs * 8 + r4;
                int cig = t * 32 + c4 + warp_n * 8 + 4 * cs;
                out[((b * HC + cig) * HH + s) * WW + w] = h;
                An[(w + 1) * AST + cig] = h;
            }
        __syncthreads();   // own An slice staged

        // ---- broadcast own 32-ci slice (rows 1..64) to the 3 peers, b64 ----
        for (int idx = tid; idx < 1024; idx += NTHR) {
            int row = (idx >> 4) + 1;
            int cp  = (idx & 15) << 1;
            unsigned off = AnB + (unsigned)((row * AST + t * 32 + cp) * 4);
            unsigned long long v = *(const unsigned long long*)(smc + off);
            #pragma unroll
            for (int r = 0; r < CLU; r++)
                if (r != t)
                    asm volatile("st.shared::cluster.b64 [%0], %1;"
                                 :: "r"(peer[r] + off), "l"(v) : "memory");
        }

        // single cluster barrier per step: A(s+1) complete everywhere
        asm volatile("barrier.cluster.arrive.aligned;" ::: "memory");
        asm volatile("barrier.cluster.wait.aligned;" ::: "memory");
    }
}

extern "C" void kernel_launch(void* const* d_in, const int* in_sizes, int n_in,
                              void* d_out, int out_size) {
    const float* x    = (const float*)d_in[0];
    const float* W_is = (const float*)d_in[1];
    const float* b_is = (const float*)d_in[2];
    const float* W_ss = (const float*)d_in[3];
    const float* b_ss = (const float*)d_in[4];
    const float* h0   = (const float*)d_in[5];
    const float* c0   = (const float*)d_in[6];
    float* out = (float*)d_out;

    cudaFuncSetAttribute(rowlstm_kernel,
                         cudaFuncAttributeMaxDynamicSharedMemorySize, SMEM_BYTES);
    rowlstm_kernel<<<NCTA, NTHR, SMEM_BYTES>>>(x, W_is, b_is, W_ss, b_ss, h0, c0, out);
}

// round 15
// speedup vs baseline: 2.4014x; 1.3569x over previous
#include <cuda_runtime.h>
#include <cstdint>

#define CIN   3
#define HH    64
#define WW    64
#define HC    128
#define NCTA  128
#define NTHR  512
#define CLU   4
#define AST   136                 // A row stride (floats), 136 mod 32 = 8 -> conflict-free LDS.64
#define BST   264                 // B row stride (floats), 264 mod 32 = 8

// smem byte offsets
#define WI_OFF 0                  // 7*128 floats = 3584 B
#define A0_OFF 3584               // 65 x AST floats = 35360 B
#define A1_OFF 38944
#define B_OFF  74304              // 128 x BST floats = 135168 B
#define SMEM_BYTES 209472

__device__ __forceinline__ unsigned smem_u32(const void* p) {
    unsigned a;
    asm("{ .reg .u64 t; cvta.to.shared.u64 t, %1; cvt.u32.u64 %0, t; }" : "=r"(a) : "l"(p));
    return a;
}
__device__ __forceinline__ float sigm(float v) { return 1.f / (1.f + __expf(-v)); }
__device__ __forceinline__ float rnd_tf32(float a) {
    return __uint_as_float((__float_as_uint(a) + 0x1000u) & 0xFFFFE000u);
}
// paired-k column permutation within each 8-block: pos = blk*8 + (k%4)*2 + ((k>>2)&1)
__device__ __forceinline__ int kperm(int k) {
    return (k & ~7) + ((k & 3) << 1) + ((k >> 2) & 1);
}

#define MMA(c0_,c1_,c2_,c3_,a0_,a1_,a2_,a3_,b0_,b1_) \
    asm volatile("mma.sync.aligned.m16n8k8.row.col.f32.tf32.tf32.f32 " \
        "{%0,%1,%2,%3}, {%4,%5,%6,%7}, {%8,%9}, {%0,%1,%2,%3};" \
        : "+f"(c0_), "+f"(c1_), "+f"(c2_), "+f"(c3_) \
        : "r"(a0_), "r"(a1_), "r"(a2_), "r"(a3_), "r"(b0_), "r"(b1_))

__global__ __launch_bounds__(NTHR, 1) __cluster_dims__(CLU, 1, 1)
void rowlstm_kernel(const float* __restrict__ x,
                    const float* __restrict__ W_is,
                    const float* __restrict__ b_is,
                    const float* __restrict__ W_ss,
                    const float* __restrict__ b_ss,
                    const float* __restrict__ h0,
                    const float* __restrict__ c0,
                    float* __restrict__ out)
{
    extern __shared__ char smc[];
    float* WIs = (float*)(smc + WI_OFF);
    float* Bsm = (float*)(smc + B_OFF);

    const int tid = threadIdx.x, wid = tid >> 5, lane = tid & 31;
    const int b = blockIdx.x >> 2;
    unsigned rank; asm("mov.u32 %0, %%cluster_ctarank;" : "=r"(rank));
    const int t = (int)rank;
    const unsigned sb = smem_u32(smc);

    // ---- one-time fills ----
    // B[n][paired-k]: k = tap*128 + ci, tf32-rounded weights; k permuted within 8-blocks
    // n -> (gate, ci_local): g = bit0 + 2*bit3 ; cil = bits[1:2] + 4*bit4 + 8*bits[5:6]
    for (int idx = tid; idx < HC * 256; idx += NTHR) {
        int n = idx >> 8, k = idx & 255;
        int tap = k >> 7, ci = k & 127;
        int g   = (n & 1) | (((n >> 3) & 1) << 1);
        int cil = ((n >> 1) & 3) | (((n >> 4) & 1) << 2) | (((n >> 5) & 3) << 3);
        int co  = g * HC + t * 32 + cil;
        Bsm[n * BST + tap * 128 + kperm(ci)] = rnd_tf32(W_ss[(co * HC + ci) * 3 + tap]);
    }
    for (int idx = tid; idx < 7 * 128; idx += NTHR) {
        int row = idx >> 7, n = idx & 127;
        int g   = (n & 1) | (((n >> 3) & 1) << 1);
        int cil = ((n >> 1) & 3) | (((n >> 4) & 1) << 2) | (((n >> 5) & 3) << 3);
        int co  = g * HC + t * 32 + cil;
        float v;
        if (row < 6) { int tap = row / 3, cn = row - tap * 3; v = W_is[(co * CIN + cn) * 3 + tap]; }
        else v = b_is[co] + b_ss[co];
        WIs[row * 128 + n] = v;
    }
    // A buffers: rounded h[w] at row w+1, permuted columns; row 0 = zeros (both buffers)
    for (int idx = tid; idx < 64 * 128; idx += NTHR) {
        int w = idx >> 7, ci = idx & 127;
        ((float*)(smc + A0_OFF))[(w + 1) * AST + kperm(ci)] = rnd_tf32(h0[ci * WW + w]);
    }
    for (int idx = tid; idx < 128; idx += NTHR) {
        ((float*)(smc + A0_OFF))[idx] = 0.f;
        ((float*)(smc + A1_OFF))[idx] = 0.f;
    }
    __syncthreads();

    // 16 warps: warp tile M=16 (warp_m 0..3), N=32 (warp_n 0..3)
    const int warp_m = wid >> 2, warp_n = wid & 3;
    const int m0 = warp_m * 16, n0 = warp_n * 32;
    const int r4 = lane >> 2, c4 = lane & 3;

    float creg[2][2];
    #pragma unroll
    for (int rs = 0; rs < 2; rs++)
        #pragma unroll
        for (int cs = 0; cs < 2; cs++) {
            int w   = m0 + rs * 8 + r4;
            int cig = t * 32 + c4 + warp_n * 8 + 4 * cs;
            creg[rs][cs] = c0[cig * WW + w];
        }

    unsigned peer[CLU];
    #pragma unroll
    for (int r = 0; r < CLU; r++)
        asm("mapa.shared::cluster.u32 %0, %1, %2;" : "=r"(peer[r]) : "r"(sb), "r"(r));

    // prologue cluster sync
    asm volatile("barrier.cluster.arrive.aligned;" ::: "memory");
    asm volatile("barrier.cluster.wait.aligned;" ::: "memory");

    for (int s = 0; s < HH; s++) {
        const float*   Ac  = (const float*)(smc + ((s & 1) ? A1_OFF : A0_OFF));
        float*         An  = (float*)      (smc + ((s & 1) ? A0_OFF : A1_OFF));
        const unsigned AnB = (unsigned)((s & 1) ? A0_OFF : A1_OFF);

        // ---- acc init = bias + x-projection ----
        float xv[2][6];
        #pragma unroll
        for (int rs = 0; rs < 2; rs++) {
            int w = m0 + rs * 8 + r4;
            #pragma unroll
            for (int cn = 0; cn < CIN; cn++) {
                const float* xb = x + ((b * CIN + cn) * HH + s) * WW;
                xv[rs][cn]     = (w > 0) ? xb[w - 1] : 0.f;
                xv[rs][3 + cn] = xb[w];
            }
        }
        float acc[4][4];
        #pragma unroll
        for (int n8 = 0; n8 < 4; n8++)
            #pragma unroll
            for (int pq = 0; pq < 2; pq++) {
                int ncol = n0 + n8 * 8 + 2 * c4 + pq;
                float wib = WIs[6 * 128 + ncol];
                float wir[6];
                #pragma unroll
                for (int rr = 0; rr < 6; rr++) wir[rr] = WIs[rr * 128 + ncol];
                #pragma unroll
                for (int rs = 0; rs < 2; rs++) {
                    float v = wib;
                    #pragma unroll
                    for (int rr = 0; rr < 6; rr++) v += xv[rs][rr] * wir[rr];
                    acc[n8][pq + 2 * rs] = v;
                }
            }

        // ---- GEMM: 32 k8-steps, all-LDS.64, pre-rounded A and B ----
        #pragma unroll 4
        for (int ks = 0; ks < 32; ks++) {
            int tap = ks >> 4;
            int kc  = (ks & 15) * 8;
            float2 aA = *(const float2*)(Ac + (m0 + r4 + tap) * AST + kc + 2 * c4);      // a0, a2
            float2 aB = *(const float2*)(Ac + (m0 + r4 + tap + 8) * AST + kc + 2 * c4);  // a1, a3
            unsigned a0 = __float_as_uint(aA.x), a2 = __float_as_uint(aA.y);
            unsigned a1 = __float_as_uint(aB.x), a3 = __float_as_uint(aB.y);
            const float* bb = Bsm + (n0 + r4) * BST + tap * 128 + kc + 2 * c4;
            #pragma unroll
            for (int n8 = 0; n8 < 4; n8++) {
                float2 bv = *(const float2*)(bb + n8 * 8 * BST);
                MMA(acc[n8][0], acc[n8][1], acc[n8][2], acc[n8][3],
                    a0, a1, a2, a3, __float_as_uint(bv.x), __float_as_uint(bv.y));
            }
        }

        // ---- epilogue: gates -> c,h; out + local stage (rounded, permuted) ----
        #pragma unroll
        for (int rs = 0; rs < 2; rs++)
            #pragma unroll
            for (int cs = 0; cs < 2; cs++) {
                float o  = sigm(acc[2 * cs][2 * rs]);
                float f  = sigm(acc[2 * cs][2 * rs + 1]);
                float ii = sigm(acc[2 * cs + 1][2 * rs]);
                float gg = sigm(acc[2 * cs + 1][2 * rs + 1]);
                float cc = f * creg[rs][cs] + ii * gg;
                creg[rs][cs] = cc;
                float h = o * tanhf(cc);
                int w   = m0 + rs * 8 + r4;
                int cig = t * 32 + c4 + warp_n * 8 + 4 * cs;
                out[((b * HC + cig) * HH + s) * WW + w] = h;
                // permuted position within own 32-col slice: c4*2 + cs within 8-block
                An[(w + 1) * AST + t * 32 + warp_n * 8 + c4 * 2 + cs] = rnd_tf32(h);
            }
        __syncthreads();   // own An slice staged

        // ---- broadcast own 32-col (permuted, contiguous) slice to the 3 peers ----
        for (int idx = tid; idx < 1024; idx += NTHR) {
            int row = (idx >> 4) + 1;
            int cp  = (idx & 15) << 1;
            unsigned off = AnB + (unsigned)((row * AST + t * 32 + cp) * 4);
            unsigned long long v = *(const unsigned long long*)(smc + off);
            #pragma unroll
            for (int r = 0; r < CLU; r++)
                if (r != t)
                    asm volatile("st.shared::cluster.b64 [%0], %1;"
                                 :: "r"(peer[r] + off), "l"(v) : "memory");
        }

        // single cluster barrier per step: A(s+1) complete everywhere
        asm volatile("barrier.cluster.arrive.aligned;" ::: "memory");
        asm volatile("barrier.cluster.wait.aligned;" ::: "memory");
    }
}

extern "C" void kernel_launch(void* const* d_in, const int* in_sizes, int n_in,
                              void* d_out, int out_size) {
    const float* x    = (const float*)d_in[0];
    const float* W_is = (const float*)d_in[1];
    const float* b_is = (const float*)d_in[2];
    const float* W_ss = (const float*)d_in[3];
    const float* b_ss = (const float*)d_in[4];
    const float* h0   = (const float*)d_in[5];
    const float* c0   = (const float*)d_in[6];
    float* out = (float*)d_out;

    cudaFuncSetAttribute(rowlstm_kernel,
                         cudaFuncAttributeMaxDynamicSharedMemorySize, SMEM_BYTES);
    rowlstm_kernel<<<NCTA, NTHR, SMEM_BYTES>>>(x, W_is, b_is, W_ss, b_ss, h0, c0, out);
}

// round 16
// speedup vs baseline: 3.3843x; 1.4093x over previous
#include <cuda_runtime.h>
#include <cuda_bf16.h>
#include <cstdint>

#define CIN   3
#define HH    64
#define WW    64
#define HC    128
#define NCTA  128
#define NTHR  512
#define CLU   4
#define ASTE  144                 // A row stride (bf16 elems) = 288 B, 288 mod 128 = 32
#define BSTE  272                 // B row stride (bf16 elems) = 544 B, 544 mod 128 = 32

// smem byte offsets
#define WI_OFF 0                  // 7*128 floats = 3584 B
#define A0_OFF 3584               // 65 x 288 B = 18720 B
#define A1_OFF 22304
#define B_OFF  41024              // 128 x 544 B = 69632 B
#define SMEM_BYTES 110656

typedef __nv_bfloat16 bf16;

__device__ __forceinline__ unsigned smem_u32(const void* p) {
    unsigned a;
    asm("{ .reg .u64 t; cvta.to.shared.u64 t, %1; cvt.u32.u64 %0, t; }" : "=r"(a) : "l"(p));
    return a;
}
__device__ __forceinline__ float sigm(float v) { return 1.f / (1.f + __expf(-v)); }
// quad permutation within each 16-block: (2c,2c+1,2c+8,2c+9) stored contiguously
__device__ __forceinline__ int kperm16(int k) {
    int kk = k & 15;
    return (k & ~15) + (((kk & 7) >> 1) << 2) + (kk & 1) + (((kk >> 3) & 1) << 1);
}

#define MMA16(c0_,c1_,c2_,c3_,a0_,a1_,a2_,a3_,b0_,b1_) \
    asm volatile("mma.sync.aligned.m16n8k16.row.col.f32.bf16.bf16.f32 " \
        "{%0,%1,%2,%3}, {%4,%5,%6,%7}, {%8,%9}, {%0,%1,%2,%3};" \
        : "+f"(c0_), "+f"(c1_), "+f"(c2_), "+f"(c3_) \
        : "r"(a0_), "r"(a1_), "r"(a2_), "r"(a3_), "r"(b0_), "r"(b1_))

__global__ __launch_bounds__(NTHR, 1) __cluster_dims__(CLU, 1, 1)
void rowlstm_kernel(const float* __restrict__ x,
                    const float* __restrict__ W_is,
                    const float* __restrict__ b_is,
                    const float* __restrict__ W_ss,
                    const float* __restrict__ b_ss,
                    const float* __restrict__ h0,
                    const float* __restrict__ c0,
                    float* __restrict__ out)
{
    extern __shared__ char smc[];
    float* WIs = (float*)(smc + WI_OFF);
    bf16*  Bsm = (bf16*)(smc + B_OFF);

    const int tid = threadIdx.x, wid = tid >> 5, lane = tid & 31;
    const int b = blockIdx.x >> 2;
    unsigned rank; asm("mov.u32 %0, %%cluster_ctarank;" : "=r"(rank));
    const int t = (int)rank;
    const unsigned sb = smem_u32(smc);

    // ---- one-time fills ----
    // B[n][k]: k = tap*128 + kperm16(ci); n -> (gate, cil): g = bit0+2*bit3,
    // cil = bits[1:2] + 4*bit4 + 8*bits[5:6]
    for (int idx = tid; idx < HC * 256; idx += NTHR) {
        int n = idx >> 8, k = idx & 255;
        int tap = k >> 7, ci = k & 127;
        int g   = (n & 1) | (((n >> 3) & 1) << 1);
        int cil = ((n >> 1) & 3) | (((n >> 4) & 1) << 2) | (((n >> 5) & 3) << 3);
        int co  = g * HC + t * 32 + cil;
        Bsm[n * BSTE + tap * 128 + kperm16(ci)] = __float2bfloat16(W_ss[(co * HC + ci) * 3 + tap]);
    }
    for (int idx = tid; idx < 7 * 128; idx += NTHR) {
        int row = idx >> 7, n = idx & 127;
        int g   = (n & 1) | (((n >> 3) & 1) << 1);
        int cil = ((n >> 1) & 3) | (((n >> 4) & 1) << 2) | (((n >> 5) & 3) << 3);
        int co  = g * HC + t * 32 + cil;
        float v;
        if (row < 6) { int tap = row / 3, cn = row - tap * 3; v = W_is[(co * CIN + cn) * 3 + tap]; }
        else v = b_is[co] + b_ss[co];
        WIs[row * 128 + n] = v;
    }
    // A buffers: bf16 h[w] at row w+1, permuted cols; row 0 = zeros (both buffers)
    for (int idx = tid; idx < 64 * 128; idx += NTHR) {
        int w = idx >> 7, ci = idx & 127;
        ((bf16*)(smc + A0_OFF))[(w + 1) * ASTE + kperm16(ci)] = __float2bfloat16(h0[ci * WW + w]);
    }
    for (int idx = tid; idx < ASTE; idx += NTHR) {
        ((bf16*)(smc + A0_OFF))[idx] = __float2bfloat16(0.f);
        ((bf16*)(smc + A1_OFF))[idx] = __float2bfloat16(0.f);
    }
    __syncthreads();

    // 16 warps: warp tile M=16 (warp_m 0..3), N=32 (warp_n 0..3)
    const int warp_m = wid >> 2, warp_n = wid & 3;
    const int m0 = warp_m * 16, n0 = warp_n * 32;
    const int r4 = lane >> 2, c4 = lane & 3;

    float creg[2][2];
    int   cig_[2], spos[2];
    #pragma unroll
    for (int cs = 0; cs < 2; cs++) {
        cig_[cs] = t * 32 + c4 + warp_n * 8 + 4 * cs;
        spos[cs] = kperm16(cig_[cs]);
    }
    #pragma unroll
    for (int rs = 0; rs < 2; rs++)
        #pragma unroll
        for (int cs = 0; cs < 2; cs++) {
            int w = m0 + rs * 8 + r4;
            creg[rs][cs] = c0[cig_[cs] * WW + w];
        }

    unsigned peer[CLU];
    #pragma unroll
    for (int r = 0; r < CLU; r++)
        asm("mapa.shared::cluster.u32 %0, %1, %2;" : "=r"(peer[r]) : "r"(sb), "r"(r));

    // prologue cluster sync
    asm volatile("barrier.cluster.arrive.aligned;" ::: "memory");
    asm volatile("barrier.cluster.wait.aligned;" ::: "memory");

    for (int s = 0; s < HH; s++) {
        const bf16*    Ac  = (const bf16*)(smc + ((s & 1) ? A1_OFF : A0_OFF));
        bf16*          An  = (bf16*)      (smc + ((s & 1) ? A0_OFF : A1_OFF));
        const unsigned AnB = (unsigned)((s & 1) ? A0_OFF : A1_OFF);

        // ---- acc init = bias + x-projection (fp32 exact) ----
        float xv[2][6];
        #pragma unroll
        for (int rs = 0; rs < 2; rs++) {
            int w = m0 + rs * 8 + r4;
            #pragma unroll
            for (int cn = 0; cn < CIN; cn++) {
                const float* xb = x + ((b * CIN + cn) * HH + s) * WW;
                xv[rs][cn]     = (w > 0) ? xb[w - 1] : 0.f;
                xv[rs][3 + cn] = xb[w];
            }
        }
        float acc[4][4];
        #pragma unroll
        for (int n8 = 0; n8 < 4; n8++)
            #pragma unroll
            for (int pq = 0; pq < 2; pq++) {
                int ncol = n0 + n8 * 8 + 2 * c4 + pq;
                float wib = WIs[6 * 128 + ncol];
                float wir[6];
                #pragma unroll
                for (int rr = 0; rr < 6; rr++) wir[rr] = WIs[rr * 128 + ncol];
                #pragma unroll
                for (int rs = 0; rs < 2; rs++) {
                    float v = wib;
                    #pragma unroll
                    for (int rr = 0; rr < 6; rr++) v += xv[rs][rr] * wir[rr];
                    acc[n8][pq + 2 * rs] = v;
                }
            }

        // ---- GEMM: 16 k16-steps (8 left-tap rows w, 8 center-tap rows w+1) ----
        #pragma unroll 4
        for (int ks = 0; ks < 16; ks++) {
            int tap = ks >> 3;
            int kc  = (ks & 7) * 16 + 4 * c4;
            unsigned long long av0 = *(const unsigned long long*)(Ac + (m0 + r4 + tap) * ASTE + kc);
            unsigned long long av1 = *(const unsigned long long*)(Ac + (m0 + r4 + tap + 8) * ASTE + kc);
            unsigned a0 = (unsigned)av0, a2 = (unsigned)(av0 >> 32);
            unsigned a1 = (unsigned)av1, a3 = (unsigned)(av1 >> 32);
            const bf16* bb = Bsm + (n0 + r4) * BSTE + tap * 128 + kc;
            #pragma unroll
            for (int n8 = 0; n8 < 4; n8++) {
                unsigned long long bv = *(const unsigned long long*)(bb + n8 * 8 * BSTE);
                MMA16(acc[n8][0], acc[n8][1], acc[n8][2], acc[n8][3],
                      a0, a1, a2, a3, (unsigned)bv, (unsigned)(bv >> 32));
            }
        }

        // ---- epilogue: gates -> c,h (fp32); out + bf16 stage into An ----
        #pragma unroll
        for (int rs = 0; rs < 2; rs++)
            #pragma unroll
            for (int cs = 0; cs < 2; cs++) {
                float o  = sigm(acc[2 * cs][2 * rs]);
                float f  = sigm(acc[2 * cs][2 * rs + 1]);
                float ii = sigm(acc[2 * cs + 1][2 * rs]);
                float gg = sigm(acc[2 * cs + 1][2 * rs + 1]);
                float cc = f * creg[rs][cs] + ii * gg;
                creg[rs][cs] = cc;
                float h = o * tanhf(cc);
                int w = m0 + rs * 8 + r4;
                out[((b * HC + cig_[cs]) * HH + s) * WW + w] = h;
                An[(w + 1) * ASTE + spos[cs]] = __float2bfloat16(h);
            }
        __syncthreads();   // own An slice staged

        // ---- broadcast own 32-col (64 B/row) slice to the 3 peers, b64 ----
        {
            int row = (tid >> 3) + 1;             // 512 threads -> rows 1..64
            int i   = tid & 7;
            unsigned off = AnB + (unsigned)(row * 288 + t * 64 + i * 8);
            unsigned long long v = *(const unsigned long long*)(smc + off);
            #pragma unroll
            for (int r = 0; r < CLU; r++)
                if (r != t)
                    asm volatile("st.shared::cluster.b64 [%0], %1;"
                                 :: "r"(peer[r] + off), "l"(v) : "memory");
        }

        // single cluster barrier per step: A(s+1) complete everywhere
        asm volatile("barrier.cluster.arrive.aligned;" ::: "memory");
        asm volatile("barrier.cluster.wait.aligned;" ::: "memory");
    }
}

extern "C" void kernel_launch(void* const* d_in, const int* in_sizes, int n_in,
                              void* d_out, int out_size) {
    const float* x    = (const float*)d_in[0];
    const float* W_is = (const float*)d_in[1];
    const float* b_is = (const float*)d_in[2];
    const float* W_ss = (const float*)d_in[3];
    const float* b_ss = (const float*)d_in[4];
    const float* h0   = (const float*)d_in[5];
    const float* c0   = (const float*)d_in[6];
    float* out = (float*)d_out;

    cudaFuncSetAttribute(rowlstm_kernel,
                         cudaFuncAttributeMaxDynamicSharedMemorySize, SMEM_BYTES);
    rowlstm_kernel<<<NCTA, NTHR, SMEM_BYTES>>>(x, W_is, b_is, W_ss, b_ss, h0, c0, out);
}